// round 3
// baseline (speedup 1.0000x reference)
#include <cuda_runtime.h>
#include <cuda_bf16.h>
#include <math.h>

// Problem constants (fixed by the dataset)
#define BATCH 4
#define SEQ   1024
#define HID   1024
#define NHEAD 16
#define DHEAD 64            // HID / NHEAD
#define NTOK  (BATCH * SEQ) // 4096 rows
#define NELEM ((size_t)NTOK * HID) // 4,194,304

// ---------------------------------------------------------------------------
// Scratch: single big __device__ global (no allocations allowed).
// Layout (floats):
//  q   : [0,        4M)
//  k   : [4M,       8M)
//  v   : [8M,      12M)
//  att : [12M,     16M)
//  tmp : [16M,     20M)   (sa / ca / ff2 outputs)
//  san : [20M,     24M)   (post-LN1, q-input for cross attn)
//  h2  : [24M,     28M)   (post-LN2, FFN input + final residual)
//  ff1 : [28M,     44M)   (B*S*4H)
// ---------------------------------------------------------------------------
__device__ float g_scratch[44u * 1024u * 1024u];

// ===========================================================================
// SGEMM: C[M,N] = A[M,K] @ B[K,N] + bias[N]  (optional ReLU)
// 128x128 block tile, BK=8, 8x8 per thread, 256 threads.
// All shapes here are multiples of the tile sizes (no bounds checks needed).
// ===========================================================================
#define BM 128
#define BN 128
#define BK 8
#define TM 8
#define TN 8

__global__ __launch_bounds__(256) void sgemm_bias_kernel(
    const float* __restrict__ A, const float* __restrict__ B,
    const float* __restrict__ bias, float* __restrict__ C,
    int M, int N, int K, int relu)
{
    __shared__ float As[BK][BM];
    __shared__ float Bs[BK][BN];

    const int bn = blockIdx.x;
    const int bm = blockIdx.y;
    const int tid = threadIdx.x;

    // A tile load mapping: 128 rows x 8 cols = 256 float4 (2 per row)
    const int arow = tid >> 1;          // 0..127
    const int acol = (tid & 1) * 4;     // 0 or 4
    // B tile load mapping: 8 rows x 128 cols = 256 float4
    const int brow = tid >> 5;          // 0..7
    const int bcol = (tid & 31) * 4;    // 0..124

    const float* Aptr = A + (size_t)(bm * BM + arow) * K + acol;
    const float* Bptr = B + (size_t)brow * N + bn * BN + bcol;

    const int tr = (tid >> 4) * TM;     // 0..120
    const int tc = (tid & 15) * TN;     // 0..120

    float acc[TM][TN];
    #pragma unroll
    for (int i = 0; i < TM; i++)
        #pragma unroll
        for (int j = 0; j < TN; j++) acc[i][j] = 0.f;

    for (int k0 = 0; k0 < K; k0 += BK) {
        float4 a4 = *(const float4*)Aptr;
        As[acol + 0][arow] = a4.x;
        As[acol + 1][arow] = a4.y;
        As[acol + 2][arow] = a4.z;
        As[acol + 3][arow] = a4.w;
        *(float4*)&Bs[brow][bcol] = *(const float4*)Bptr;
        __syncthreads();

        #pragma unroll
        for (int kk = 0; kk < BK; kk++) {
            float4 a0 = *(const float4*)&As[kk][tr];
            float4 a1 = *(const float4*)&As[kk][tr + 4];
            float4 b0 = *(const float4*)&Bs[kk][tc];
            float4 b1 = *(const float4*)&Bs[kk][tc + 4];
            float af[TM] = {a0.x, a0.y, a0.z, a0.w, a1.x, a1.y, a1.z, a1.w};
            float bf[TN] = {b0.x, b0.y, b0.z, b0.w, b1.x, b1.y, b1.z, b1.w};
            #pragma unroll
            for (int i = 0; i < TM; i++)
                #pragma unroll
                for (int j = 0; j < TN; j++)
                    acc[i][j] = fmaf(af[i], bf[j], acc[i][j]);
        }
        __syncthreads();
        Aptr += BK;
        Bptr += (size_t)BK * N;
    }

    // Epilogue: bias (+relu), float4 stores
    #pragma unroll
    for (int i = 0; i < TM; i++) {
        const size_t row = (size_t)(bm * BM + tr + i);
        #pragma unroll
        for (int j = 0; j < TN; j += 4) {
            const int col = bn * BN + tc + j;
            float4 r;
            r.x = acc[i][j + 0] + bias[col + 0];
            r.y = acc[i][j + 1] + bias[col + 1];
            r.z = acc[i][j + 2] + bias[col + 2];
            r.w = acc[i][j + 3] + bias[col + 3];
            if (relu) {
                r.x = fmaxf(r.x, 0.f); r.y = fmaxf(r.y, 0.f);
                r.z = fmaxf(r.z, 0.f); r.w = fmaxf(r.w, 0.f);
            }
            *(float4*)&C[row * N + col] = r;
        }
    }
}

// ===========================================================================
// Flash attention (fp32, online softmax).
// q,k,v,out: [B, S, H] with head h at columns [h*64, h*64+64).
// Reference math quirk: logits = (q.k/sqrt(d) + add)/sqrt(d)
//                              = q.k/d + add/sqrt(d),  add = -(1-mask)*1e10
// Block: 64 queries (one (b,h,qtile)), 128 threads, K-tile = 32.
// ===========================================================================
#define QT 64
#define KT 32

__global__ __launch_bounds__(128) void flash_kernel(
    const float* __restrict__ Q, const float* __restrict__ Kmat,
    const float* __restrict__ V, const int* __restrict__ mask,
    float* __restrict__ O)
{
    const int qtile = blockIdx.x;        // 0..S/QT-1
    const int bh    = blockIdx.y;        // 0..B*NHEAD-1
    const int b = bh / NHEAD;
    const int h = bh % NHEAD;
    const int tid = threadIdx.x;

    __shared__ float Qs[QT][DHEAD];          // 16 KB
    __shared__ float Ks[KT][DHEAD + 4];      // padded (keeps 16B row alignment)
    __shared__ float Vs[KT][DHEAD];
    __shared__ float Ps[QT][KT + 1];         // logits / probs
    __shared__ float mrow[QT], lrow[QT], arow[QT];
    __shared__ float madd[KT];

    // Load Q tile (64x64 floats = 1024 float4)
    const float* qbase = Q + ((size_t)b * SEQ + (size_t)qtile * QT) * HID + h * DHEAD;
    for (int i = tid; i < QT * (DHEAD / 4); i += 128) {
        int r = i / (DHEAD / 4), c4 = i % (DHEAD / 4);
        ((float4*)&Qs[r][0])[c4] = *(const float4*)(qbase + (size_t)r * HID + c4 * 4);
    }
    if (tid < QT) { mrow[tid] = -INFINITY; lrow[tid] = 0.f; }

    const int trS = (tid >> 3) * 4;   // score rows: 4 per thread
    const int tcS = (tid & 7) * 4;    // score cols: 4 per thread (of KT=32)
    const int trO = trS;              // O rows: same 4 rows
    const int tcO = (tid & 7) * 8;    // O cols: 8 per thread (of D=64)

    float acc[4][8];
    #pragma unroll
    for (int i = 0; i < 4; i++)
        #pragma unroll
        for (int j = 0; j < 8; j++) acc[i][j] = 0.f;

    const float inv_d = 1.0f / (float)DHEAD;          // 1/64 (combined double scale)
    const float inv_s = -1.0e10f / 8.0f;              // add / sqrt(d)

    for (int k0 = 0; k0 < SEQ; k0 += KT) {
        // Load K,V tiles (each 32x64 = 512 float4 -> 4 per thread)
        const float* kbase = Kmat + ((size_t)b * SEQ + k0) * HID + h * DHEAD;
        const float* vbase = V    + ((size_t)b * SEQ + k0) * HID + h * DHEAD;
        for (int i = tid; i < KT * (DHEAD / 4); i += 128) {
            int r = i / (DHEAD / 4), c4 = i % (DHEAD / 4);
            ((float4*)&Ks[r][0])[c4] = *(const float4*)(kbase + (size_t)r * HID + c4 * 4);
            ((float4*)&Vs[r][0])[c4] = *(const float4*)(vbase + (size_t)r * HID + c4 * 4);
        }
        if (tid < KT) {
            madd[tid] = (mask[b * SEQ + k0 + tid] != 0) ? 0.f : inv_s;
        }
        __syncthreads();

        // Scores: each thread 4x4 of the 64x32 tile
        float s[4][4];
        #pragma unroll
        for (int i = 0; i < 4; i++)
            #pragma unroll
            for (int j = 0; j < 4; j++) s[i][j] = 0.f;
        #pragma unroll 8
        for (int kk = 0; kk < DHEAD; kk++) {
            float qf[4], kf[4];
            #pragma unroll
            for (int i = 0; i < 4; i++) qf[i] = Qs[trS + i][kk];
            #pragma unroll
            for (int j = 0; j < 4; j++) kf[j] = Ks[tcS + j][kk];
            #pragma unroll
            for (int i = 0; i < 4; i++)
                #pragma unroll
                for (int j = 0; j < 4; j++)
                    s[i][j] = fmaf(qf[i], kf[j], s[i][j]);
        }
        #pragma unroll
        for (int i = 0; i < 4; i++)
            #pragma unroll
            for (int j = 0; j < 4; j++)
                Ps[trS + i][tcS + j] = s[i][j] * inv_d + madd[tcS + j];
        __syncthreads();

        // Per-row online softmax pass (one thread per query row)
        if (tid < QT) {
            float m_old = mrow[tid];
            float mx = m_old;
            float* pr = &Ps[tid][0];
            #pragma unroll
            for (int j = 0; j < KT; j++) mx = fmaxf(mx, pr[j]);
            float alpha = __expf(m_old - mx);   // m_old=-inf -> 0 on first tile
            float sum = 0.f;
            #pragma unroll
            for (int j = 0; j < KT; j++) {
                float p = __expf(pr[j] - mx);
                pr[j] = p;
                sum += p;
            }
            mrow[tid] = mx;
            lrow[tid] = lrow[tid] * alpha + sum;
            arow[tid] = alpha;
        }
        __syncthreads();

        // Rescale accumulators + accumulate P @ V
        #pragma unroll
        for (int i = 0; i < 4; i++) {
            float al = arow[trO + i];
            #pragma unroll
            for (int j = 0; j < 8; j++) acc[i][j] *= al;
        }
        #pragma unroll 4
        for (int kk = 0; kk < KT; kk++) {
            float4 v0 = *(const float4*)&Vs[kk][tcO];
            float4 v1 = *(const float4*)&Vs[kk][tcO + 4];
            float vf[8] = {v0.x, v0.y, v0.z, v0.w, v1.x, v1.y, v1.z, v1.w};
            #pragma unroll
            for (int i = 0; i < 4; i++) {
                float p = Ps[trO + i][kk];
                #pragma unroll
                for (int j = 0; j < 8; j++)
                    acc[i][j] = fmaf(p, vf[j], acc[i][j]);
            }
        }
        __syncthreads();   // before next tile overwrites Ks/Vs/Ps/madd
    }

    // Write normalized output
    float* obase = O + ((size_t)b * SEQ + (size_t)qtile * QT) * HID + h * DHEAD;
    #pragma unroll
    for (int i = 0; i < 4; i++) {
        float invl = 1.0f / lrow[trO + i];
        float4 r0, r1;
        r0.x = acc[i][0] * invl; r0.y = acc[i][1] * invl;
        r0.z = acc[i][2] * invl; r0.w = acc[i][3] * invl;
        r1.x = acc[i][4] * invl; r1.y = acc[i][5] * invl;
        r1.z = acc[i][6] * invl; r1.w = acc[i][7] * invl;
        float* po = obase + (size_t)(trO + i) * HID + tcO;
        *(float4*)po = r0;
        *(float4*)(po + 4) = r1;
    }
}

// ===========================================================================
// Fused residual-add + LayerNorm: out = g * (x - mean)/sqrt(var+eps) + b,
// x = a + resid. One block (256 threads) per row of H=1024.
// ===========================================================================
__device__ __forceinline__ float block_sum256(float v, float* sh)
{
    const int lane = threadIdx.x & 31;
    const int wid  = threadIdx.x >> 5;
    #pragma unroll
    for (int o = 16; o > 0; o >>= 1) v += __shfl_xor_sync(0xffffffffu, v, o);
    if (lane == 0) sh[wid] = v;
    __syncthreads();
    if (wid == 0) {
        float t = (lane < 8) ? sh[lane] : 0.f;
        #pragma unroll
        for (int o = 4; o > 0; o >>= 1) t += __shfl_xor_sync(0xffffffffu, t, o);
        if (lane == 0) sh[0] = t;
    }
    __syncthreads();
    float r = sh[0];
    __syncthreads();
    return r;
}

__global__ __launch_bounds__(256) void add_ln_kernel(
    const float* __restrict__ a, const float* __restrict__ resid,
    const float* __restrict__ g, const float* __restrict__ b,
    float* __restrict__ out)
{
    __shared__ float sh[32];
    const size_t row = blockIdx.x;
    const int t = threadIdx.x;

    float4 va = ((const float4*)(a + row * HID))[t];
    float4 vr = ((const float4*)(resid + row * HID))[t];
    float4 v = {va.x + vr.x, va.y + vr.y, va.z + vr.z, va.w + vr.w};

    float tot = block_sum256(v.x + v.y + v.z + v.w, sh);
    const float mean = tot * (1.0f / HID);

    float4 d = {v.x - mean, v.y - mean, v.z - mean, v.w - mean};
    float tot2 = block_sum256(d.x*d.x + d.y*d.y + d.z*d.z + d.w*d.w, sh);
    const float inv = rsqrtf(tot2 * (1.0f / HID) + 1e-5f);

    float4 vg = ((const float4*)g)[t];
    float4 vb = ((const float4*)b)[t];
    float4 o;
    o.x = vg.x * d.x * inv + vb.x;
    o.y = vg.y * d.y * inv + vb.y;
    o.z = vg.z * d.z * inv + vb.z;
    o.w = vg.w * d.w * inv + vb.w;
    ((float4*)(out + row * HID))[t] = o;
}

// ===========================================================================
// Host orchestration
// ===========================================================================
extern "C" void kernel_launch(void* const* d_in, const int* in_sizes, int n_in,
                              void* d_out, int out_size)
{
    (void)in_sizes; (void)n_in; (void)out_size;

    const float* x     = (const float*)d_in[0];   // hidden_states
    const int*   smask = (const int*)  d_in[1];   // self_att_mask
    const float* cx    = (const float*)d_in[2];   // cross_hidden_states
    const int*   cmask = (const int*)  d_in[3];   // cross_att_mask
    // d_in[4] = num_head (unused; fixed 16)
    const float* sWq = (const float*)d_in[5],  *sbq = (const float*)d_in[6];
    const float* sWk = (const float*)d_in[7],  *sbk = (const float*)d_in[8];
    const float* sWv = (const float*)d_in[9],  *sbv = (const float*)d_in[10];
    const float* sWo = (const float*)d_in[11], *sbo = (const float*)d_in[12];
    const float* cWq = (const float*)d_in[13], *cbq = (const float*)d_in[14];
    const float* cWk = (const float*)d_in[15], *cbk = (const float*)d_in[16];
    const float* cWv = (const float*)d_in[17], *cbv = (const float*)d_in[18];
    const float* cWo = (const float*)d_in[19], *cbo = (const float*)d_in[20];
    const float* g   = (const float*)d_in[21], *bb  = (const float*)d_in[22];
    const float* W1  = (const float*)d_in[23], *b1  = (const float*)d_in[24];
    const float* W2  = (const float*)d_in[25], *b2  = (const float*)d_in[26];
    float* out = (float*)d_out;

    float* base = nullptr;
    cudaGetSymbolAddress((void**)&base, g_scratch);
    float* q   = base;
    float* k   = base + 1 * NELEM;
    float* v   = base + 2 * NELEM;
    float* att = base + 3 * NELEM;
    float* tmp = base + 4 * NELEM;
    float* san = base + 5 * NELEM;
    float* h2  = base + 6 * NELEM;
    float* ff1 = base + 7 * NELEM;   // 4x wide

    const dim3 gHH(HID / BN, NTOK / BM);          // (8, 32)  for H x H GEMMs
    const dim3 gF1(4 * HID / BN, NTOK / BM);      // (32, 32) for H -> 4H
    const dim3 gF2(HID / BN, NTOK / BM);          // (8, 32)  for 4H -> H
    const dim3 gFl(SEQ / QT, BATCH * NHEAD);      // (16, 64) flash

    // ---- Self attention ----
    sgemm_bias_kernel<<<gHH, 256>>>(x, sWq, sbq, q, NTOK, HID, HID, 0);
    sgemm_bias_kernel<<<gHH, 256>>>(x, sWk, sbk, k, NTOK, HID, HID, 0);
    sgemm_bias_kernel<<<gHH, 256>>>(x, sWv, sbv, v, NTOK, HID, HID, 0);
    flash_kernel<<<gFl, 128>>>(q, k, v, smask, att);
    sgemm_bias_kernel<<<gHH, 256>>>(att, sWo, sbo, tmp, NTOK, HID, HID, 0);
    add_ln_kernel<<<NTOK, 256>>>(tmp, x, g, bb, san);

    // ---- Cross attention (q from san; k,v from cross_hidden_states) ----
    sgemm_bias_kernel<<<gHH, 256>>>(san, cWq, cbq, q, NTOK, HID, HID, 0);
    sgemm_bias_kernel<<<gHH, 256>>>(cx,  cWk, cbk, k, NTOK, HID, HID, 0);
    sgemm_bias_kernel<<<gHH, 256>>>(cx,  cWv, cbv, v, NTOK, HID, HID, 0);
    flash_kernel<<<gFl, 128>>>(q, k, v, cmask, att);
    sgemm_bias_kernel<<<gHH, 256>>>(att, cWo, cbo, tmp, NTOK, HID, HID, 0);
    // NOTE: residual uses the ORIGINAL hidden_states (matches reference)
    add_ln_kernel<<<NTOK, 256>>>(tmp, x, g, bb, h2);

    // ---- FFN ----
    sgemm_bias_kernel<<<gF1, 256>>>(h2,  W1, b1, ff1, NTOK, 4 * HID, HID, 1);
    sgemm_bias_kernel<<<gF2, 256>>>(ff1, W2, b2, tmp, NTOK, HID, 4 * HID, 0);
    add_ln_kernel<<<NTOK, 256>>>(tmp, h2, g, bb, out);
}

// round 5
// speedup vs baseline: 1.6657x; 1.6657x over previous
#include <cuda_runtime.h>
#include <cuda_bf16.h>
#include <math.h>
#include <stdint.h>

// Problem constants (fixed by the dataset)
#define BATCH 4
#define SEQ   1024
#define HID   1024
#define NHEAD 16
#define DHEAD 64            // HID / NHEAD
#define NTOK  (BATCH * SEQ) // 4096 rows
#define NELEM ((size_t)NTOK * HID) // 4,194,304

// ---------------------------------------------------------------------------
// Scratch: single big __device__ global (no allocations allowed).
// ---------------------------------------------------------------------------
__device__ float g_scratch[44u * 1024u * 1024u];

// ===========================================================================
// TF32 tensor-core GEMM: C[M,N] = A[M,K] @ B[K,N] + bias[N] (optional ReLU)
// 128x128 block tile, BK=16, 8 warps (2x4), 64x32 per warp via m16n8k8 mma.
// cp.async double-buffered. A smem [m][k] stride 20, B smem [k][n] stride 136
// -> all fragment LDS are bank-conflict-free.
// M,N,K are multiples of the tile sizes (no bounds checks needed).
// ===========================================================================
#define GAS 20    // As row stride (floats): banks {20*g+tig} conflict-free
#define GBS 136   // Bs row stride (floats): banks {8*tig+g} conflict-free

__device__ __forceinline__ uint32_t f2tf32(float x) {
    uint32_t r;
    asm("cvt.rna.tf32.f32 %0, %1;" : "=r"(r) : "f"(x));
    return r;
}

__device__ __forceinline__ void mma_tf32(float* c, const uint32_t* a, const uint32_t* b) {
    asm volatile(
        "mma.sync.aligned.m16n8k8.row.col.f32.tf32.tf32.f32 "
        "{%0,%1,%2,%3}, {%4,%5,%6,%7}, {%8,%9}, {%0,%1,%2,%3};"
        : "+f"(c[0]), "+f"(c[1]), "+f"(c[2]), "+f"(c[3])
        : "r"(a[0]), "r"(a[1]), "r"(a[2]), "r"(a[3]), "r"(b[0]), "r"(b[1]));
}

__device__ __forceinline__ void cp_async16(void* smem_dst, const void* gmem_src) {
    uint32_t s = (uint32_t)__cvta_generic_to_shared(smem_dst);
    asm volatile("cp.async.cg.shared.global [%0], [%1], 16;\n" :: "r"(s), "l"(gmem_src));
}

__global__ __launch_bounds__(256) void gemm_tf32_kernel(
    const float* __restrict__ A, const float* __restrict__ B,
    const float* __restrict__ bias, float* __restrict__ C,
    int M, int N, int K, int relu)
{
    __shared__ float As[2][128][GAS];   // [m][k], 2 stages
    __shared__ float Bs[2][16][GBS];    // [k][n], 2 stages

    const int tid  = threadIdx.x;
    const int bn   = blockIdx.x;
    const int bm   = blockIdx.y;
    const int warp = tid >> 5;
    const int lane = tid & 31;
    const int g    = lane >> 2;   // group id 0..7
    const int tig  = lane & 3;    // thread in group 0..3
    const int wm   = warp >> 2;   // 0..1
    const int wn   = warp & 3;    // 0..3

    float acc[4][4][4];
    #pragma unroll
    for (int mt = 0; mt < 4; mt++)
        #pragma unroll
        for (int nt = 0; nt < 4; nt++)
            #pragma unroll
            for (int r = 0; r < 4; r++) acc[mt][nt][r] = 0.f;

    const int nk = K >> 4;   // BK = 16

    // Prefetch one BK tile into stage s. 256 threads x 2 chunks of 16B each
    // for A (128x16 fp32) and B (16x128 fp32).
    auto prefetch = [&](int kt, int s) {
        #pragma unroll
        for (int i = 0; i < 2; i++) {
            int c = tid * 2 + i;
            int ar = c >> 2, ac = (c & 3) * 4;            // A: row 0..127, col chunk
            cp_async16(&As[s][ar][ac],
                       A + (size_t)(bm * 128 + ar) * K + kt * 16 + ac);
            int br = c >> 5, bc = (c & 31) * 4;           // B: row 0..15, col chunk
            cp_async16(&Bs[s][br][bc],
                       B + (size_t)(kt * 16 + br) * N + bn * 128 + bc);
        }
        asm volatile("cp.async.commit_group;\n");
    };

    prefetch(0, 0);

    for (int kt = 0; kt < nk; kt++) {
        const int s = kt & 1;
        if (kt + 1 < nk) {
            prefetch(kt + 1, s ^ 1);
            asm volatile("cp.async.wait_group 1;\n");
        } else {
            asm volatile("cp.async.wait_group 0;\n");
        }
        __syncthreads();

        #pragma unroll
        for (int ks = 0; ks < 16; ks += 8) {
            uint32_t af[4][4], bf[4][2];
            #pragma unroll
            for (int mt = 0; mt < 4; mt++) {
                const int r0 = wm * 64 + mt * 16 + g;
                af[mt][0] = f2tf32(As[s][r0    ][ks + tig]);
                af[mt][1] = f2tf32(As[s][r0 + 8][ks + tig]);
                af[mt][2] = f2tf32(As[s][r0    ][ks + tig + 4]);
                af[mt][3] = f2tf32(As[s][r0 + 8][ks + tig + 4]);
            }
            #pragma unroll
            for (int nt = 0; nt < 4; nt++) {
                const int c0 = wn * 32 + nt * 8 + g;
                bf[nt][0] = f2tf32(Bs[s][ks + tig    ][c0]);
                bf[nt][1] = f2tf32(Bs[s][ks + tig + 4][c0]);
            }
            #pragma unroll
            for (int mt = 0; mt < 4; mt++)
                #pragma unroll
                for (int nt = 0; nt < 4; nt++)
                    mma_tf32(acc[mt][nt], af[mt], bf[nt]);
        }
        __syncthreads();
    }

    // Epilogue: bias (+relu), float2 stores (c0,c1 are adjacent columns)
    #pragma unroll
    for (int mt = 0; mt < 4; mt++) {
        const size_t row0 = (size_t)(bm * 128 + wm * 64 + mt * 16 + g);
        #pragma unroll
        for (int nt = 0; nt < 4; nt++) {
            const int col = bn * 128 + wn * 32 + nt * 8 + 2 * tig;
            const float bv0 = bias[col], bv1 = bias[col + 1];
            float2 r0 = {acc[mt][nt][0] + bv0, acc[mt][nt][1] + bv1};
            float2 r1 = {acc[mt][nt][2] + bv0, acc[mt][nt][3] + bv1};
            if (relu) {
                r0.x = fmaxf(r0.x, 0.f); r0.y = fmaxf(r0.y, 0.f);
                r1.x = fmaxf(r1.x, 0.f); r1.y = fmaxf(r1.y, 0.f);
            }
            *(float2*)&C[row0 * N + col]       = r0;
            *(float2*)&C[(row0 + 8) * N + col] = r1;
        }
    }
}

// ===========================================================================
// Flash attention (fp32, online softmax). Unchanged from R3 (passing).
// Reference math quirk: logits = q.k/d + (1-mask)*(-1e10)/sqrt(d)
// ===========================================================================
#define QT 64
#define KT 32

__global__ __launch_bounds__(128) void flash_kernel(
    const float* __restrict__ Q, const float* __restrict__ Kmat,
    const float* __restrict__ V, const int* __restrict__ mask,
    float* __restrict__ O)
{
    const int qtile = blockIdx.x;
    const int bh    = blockIdx.y;
    const int b = bh / NHEAD;
    const int h = bh % NHEAD;
    const int tid = threadIdx.x;

    __shared__ float Qs[QT][DHEAD];
    __shared__ float Ks[KT][DHEAD + 4];
    __shared__ float Vs[KT][DHEAD];
    __shared__ float Ps[QT][KT + 1];
    __shared__ float mrow[QT], lrow[QT], arow[QT];
    __shared__ float madd[KT];

    const float* qbase = Q + ((size_t)b * SEQ + (size_t)qtile * QT) * HID + h * DHEAD;
    for (int i = tid; i < QT * (DHEAD / 4); i += 128) {
        int r = i / (DHEAD / 4), c4 = i % (DHEAD / 4);
        ((float4*)&Qs[r][0])[c4] = *(const float4*)(qbase + (size_t)r * HID + c4 * 4);
    }
    if (tid < QT) { mrow[tid] = -INFINITY; lrow[tid] = 0.f; }

    const int trS = (tid >> 3) * 4;
    const int tcS = (tid & 7) * 4;
    const int trO = trS;
    const int tcO = (tid & 7) * 8;

    float acc[4][8];
    #pragma unroll
    for (int i = 0; i < 4; i++)
        #pragma unroll
        for (int j = 0; j < 8; j++) acc[i][j] = 0.f;

    const float inv_d = 1.0f / (float)DHEAD;
    const float inv_s = -1.0e10f / 8.0f;

    for (int k0 = 0; k0 < SEQ; k0 += KT) {
        const float* kbase = Kmat + ((size_t)b * SEQ + k0) * HID + h * DHEAD;
        const float* vbase = V    + ((size_t)b * SEQ + k0) * HID + h * DHEAD;
        for (int i = tid; i < KT * (DHEAD / 4); i += 128) {
            int r = i / (DHEAD / 4), c4 = i % (DHEAD / 4);
            ((float4*)&Ks[r][0])[c4] = *(const float4*)(kbase + (size_t)r * HID + c4 * 4);
            ((float4*)&Vs[r][0])[c4] = *(const float4*)(vbase + (size_t)r * HID + c4 * 4);
        }
        if (tid < KT) {
            madd[tid] = (mask[b * SEQ + k0 + tid] != 0) ? 0.f : inv_s;
        }
        __syncthreads();

        float s[4][4];
        #pragma unroll
        for (int i = 0; i < 4; i++)
            #pragma unroll
            for (int j = 0; j < 4; j++) s[i][j] = 0.f;
        #pragma unroll 8
        for (int kk = 0; kk < DHEAD; kk++) {
            float qf[4], kf[4];
            #pragma unroll
            for (int i = 0; i < 4; i++) qf[i] = Qs[trS + i][kk];
            #pragma unroll
            for (int j = 0; j < 4; j++) kf[j] = Ks[tcS + j][kk];
            #pragma unroll
            for (int i = 0; i < 4; i++)
                #pragma unroll
                for (int j = 0; j < 4; j++)
                    s[i][j] = fmaf(qf[i], kf[j], s[i][j]);
        }
        #pragma unroll
        for (int i = 0; i < 4; i++)
            #pragma unroll
            for (int j = 0; j < 4; j++)
                Ps[trS + i][tcS + j] = s[i][j] * inv_d + madd[tcS + j];
        __syncthreads();

        if (tid < QT) {
            float m_old = mrow[tid];
            float mx = m_old;
            float* pr = &Ps[tid][0];
            #pragma unroll
            for (int j = 0; j < KT; j++) mx = fmaxf(mx, pr[j]);
            float alpha = __expf(m_old - mx);
            float sum = 0.f;
            #pragma unroll
            for (int j = 0; j < KT; j++) {
                float p = __expf(pr[j] - mx);
                pr[j] = p;
                sum += p;
            }
            mrow[tid] = mx;
            lrow[tid] = lrow[tid] * alpha + sum;
            arow[tid] = alpha;
        }
        __syncthreads();

        #pragma unroll
        for (int i = 0; i < 4; i++) {
            float al = arow[trO + i];
            #pragma unroll
            for (int j = 0; j < 8; j++) acc[i][j] *= al;
        }
        #pragma unroll 4
        for (int kk = 0; kk < KT; kk++) {
            float4 v0 = *(const float4*)&Vs[kk][tcO];
            float4 v1 = *(const float4*)&Vs[kk][tcO + 4];
            float vf[8] = {v0.x, v0.y, v0.z, v0.w, v1.x, v1.y, v1.z, v1.w};
            #pragma unroll
            for (int i = 0; i < 4; i++) {
                float p = Ps[trO + i][kk];
                #pragma unroll
                for (int j = 0; j < 8; j++)
                    acc[i][j] = fmaf(p, vf[j], acc[i][j]);
            }
        }
        __syncthreads();
    }

    float* obase = O + ((size_t)b * SEQ + (size_t)qtile * QT) * HID + h * DHEAD;
    #pragma unroll
    for (int i = 0; i < 4; i++) {
        float invl = 1.0f / lrow[trO + i];
        float4 r0, r1;
        r0.x = acc[i][0] * invl; r0.y = acc[i][1] * invl;
        r0.z = acc[i][2] * invl; r0.w = acc[i][3] * invl;
        r1.x = acc[i][4] * invl; r1.y = acc[i][5] * invl;
        r1.z = acc[i][6] * invl; r1.w = acc[i][7] * invl;
        float* po = obase + (size_t)(trO + i) * HID + tcO;
        *(float4*)po = r0;
        *(float4*)(po + 4) = r1;
    }
}

// ===========================================================================
// Fused residual-add + LayerNorm (unchanged)
// ===========================================================================
__device__ __forceinline__ float block_sum256(float v, float* sh)
{
    const int lane = threadIdx.x & 31;
    const int wid  = threadIdx.x >> 5;
    #pragma unroll
    for (int o = 16; o > 0; o >>= 1) v += __shfl_xor_sync(0xffffffffu, v, o);
    if (lane == 0) sh[wid] = v;
    __syncthreads();
    if (wid == 0) {
        float t = (lane < 8) ? sh[lane] : 0.f;
        #pragma unroll
        for (int o = 4; o > 0; o >>= 1) t += __shfl_xor_sync(0xffffffffu, t, o);
        if (lane == 0) sh[0] = t;
    }
    __syncthreads();
    float r = sh[0];
    __syncthreads();
    return r;
}

__global__ __launch_bounds__(256) void add_ln_kernel(
    const float* __restrict__ a, const float* __restrict__ resid,
    const float* __restrict__ g, const float* __restrict__ b,
    float* __restrict__ out)
{
    __shared__ float sh[32];
    const size_t row = blockIdx.x;
    const int t = threadIdx.x;

    float4 va = ((const float4*)(a + row * HID))[t];
    float4 vr = ((const float4*)(resid + row * HID))[t];
    float4 v = {va.x + vr.x, va.y + vr.y, va.z + vr.z, va.w + vr.w};

    float tot = block_sum256(v.x + v.y + v.z + v.w, sh);
    const float mean = tot * (1.0f / HID);

    float4 d = {v.x - mean, v.y - mean, v.z - mean, v.w - mean};
    float tot2 = block_sum256(d.x*d.x + d.y*d.y + d.z*d.z + d.w*d.w, sh);
    const float inv = rsqrtf(tot2 * (1.0f / HID) + 1e-5f);

    float4 vg = ((const float4*)g)[t];
    float4 vb = ((const float4*)b)[t];
    float4 o;
    o.x = vg.x * d.x * inv + vb.x;
    o.y = vg.y * d.y * inv + vb.y;
    o.z = vg.z * d.z * inv + vb.z;
    o.w = vg.w * d.w * inv + vb.w;
    ((float4*)(out + row * HID))[t] = o;
}

// ===========================================================================
// Host orchestration
// ===========================================================================
extern "C" void kernel_launch(void* const* d_in, const int* in_sizes, int n_in,
                              void* d_out, int out_size)
{
    (void)in_sizes; (void)n_in; (void)out_size;

    const float* x     = (const float*)d_in[0];
    const int*   smask = (const int*)  d_in[1];
    const float* cx    = (const float*)d_in[2];
    const int*   cmask = (const int*)  d_in[3];
    const float* sWq = (const float*)d_in[5],  *sbq = (const float*)d_in[6];
    const float* sWk = (const float*)d_in[7],  *sbk = (const float*)d_in[8];
    const float* sWv = (const float*)d_in[9],  *sbv = (const float*)d_in[10];
    const float* sWo = (const float*)d_in[11], *sbo = (const float*)d_in[12];
    const float* cWq = (const float*)d_in[13], *cbq = (const float*)d_in[14];
    const float* cWk = (const float*)d_in[15], *cbk = (const float*)d_in[16];
    const float* cWv = (const float*)d_in[17], *cbv = (const float*)d_in[18];
    const float* cWo = (const float*)d_in[19], *cbo = (const float*)d_in[20];
    const float* g   = (const float*)d_in[21], *bb  = (const float*)d_in[22];
    const float* W1  = (const float*)d_in[23], *b1  = (const float*)d_in[24];
    const float* W2  = (const float*)d_in[25], *b2  = (const float*)d_in[26];
    float* out = (float*)d_out;

    float* base = nullptr;
    cudaGetSymbolAddress((void**)&base, g_scratch);
    float* q   = base;
    float* k   = base + 1 * NELEM;
    float* v   = base + 2 * NELEM;
    float* att = base + 3 * NELEM;
    float* tmp = base + 4 * NELEM;
    float* san = base + 5 * NELEM;
    float* h2  = base + 6 * NELEM;
    float* ff1 = base + 7 * NELEM;   // 4x wide

    const dim3 gHH(HID / 128, NTOK / 128);          // (8, 32)
    const dim3 gF1(4 * HID / 128, NTOK / 128);      // (32, 32)
    const dim3 gF2(HID / 128, NTOK / 128);          // (8, 32)
    const dim3 gFl(SEQ / QT, BATCH * NHEAD);        // (16, 64)

    // ---- Self attention ----
    gemm_tf32_kernel<<<gHH, 256>>>(x, sWq, sbq, q, NTOK, HID, HID, 0);
    gemm_tf32_kernel<<<gHH, 256>>>(x, sWk, sbk, k, NTOK, HID, HID, 0);
    gemm_tf32_kernel<<<gHH, 256>>>(x, sWv, sbv, v, NTOK, HID, HID, 0);
    flash_kernel<<<gFl, 128>>>(q, k, v, smask, att);
    gemm_tf32_kernel<<<gHH, 256>>>(att, sWo, sbo, tmp, NTOK, HID, HID, 0);
    add_ln_kernel<<<NTOK, 256>>>(tmp, x, g, bb, san);

    // ---- Cross attention ----
    gemm_tf32_kernel<<<gHH, 256>>>(san, cWq, cbq, q, NTOK, HID, HID, 0);
    gemm_tf32_kernel<<<gHH, 256>>>(cx,  cWk, cbk, k, NTOK, HID, HID, 0);
    gemm_tf32_kernel<<<gHH, 256>>>(cx,  cWv, cbv, v, NTOK, HID, HID, 0);
    flash_kernel<<<gFl, 128>>>(q, k, v, cmask, att);
    gemm_tf32_kernel<<<gHH, 256>>>(att, cWo, cbo, tmp, NTOK, HID, HID, 0);
    // residual uses ORIGINAL hidden_states (matches reference)
    add_ln_kernel<<<NTOK, 256>>>(tmp, x, g, bb, h2);

    // ---- FFN ----
    gemm_tf32_kernel<<<gF1, 256>>>(h2,  W1, b1, ff1, NTOK, 4 * HID, HID, 1);
    gemm_tf32_kernel<<<gF2, 256>>>(ff1, W2, b2, tmp, NTOK, HID, 4 * HID, 0);
    add_ln_kernel<<<NTOK, 256>>>(tmp, h2, g, bb, out);
}

// round 6
// speedup vs baseline: 3.2214x; 1.9340x over previous
#include <cuda_runtime.h>
#include <cuda_bf16.h>
#include <math.h>
#include <stdint.h>

// Problem constants (fixed by the dataset)
#define BATCH 4
#define SEQ   1024
#define HID   1024
#define NHEAD 16
#define DHEAD 64            // HID / NHEAD
#define NTOK  (BATCH * SEQ) // 4096 rows
#define NELEM ((size_t)NTOK * HID) // 4,194,304

// ---------------------------------------------------------------------------
// Scratch: single big __device__ global (no allocations allowed).
// ---------------------------------------------------------------------------
__device__ float g_scratch[44u * 1024u * 1024u];

// ---------------------------------------------------------------------------
// Common tf32 mma helpers
// ---------------------------------------------------------------------------
__device__ __forceinline__ uint32_t f2tf32(float x) {
    uint32_t r;
    asm("cvt.rna.tf32.f32 %0, %1;" : "=r"(r) : "f"(x));
    return r;
}

__device__ __forceinline__ void mma_tf32(float* c, const uint32_t* a, const uint32_t* b) {
    asm volatile(
        "mma.sync.aligned.m16n8k8.row.col.f32.tf32.tf32.f32 "
        "{%0,%1,%2,%3}, {%4,%5,%6,%7}, {%8,%9}, {%0,%1,%2,%3};"
        : "+f"(c[0]), "+f"(c[1]), "+f"(c[2]), "+f"(c[3])
        : "r"(a[0]), "r"(a[1]), "r"(a[2]), "r"(a[3]), "r"(b[0]), "r"(b[1]));
}

__device__ __forceinline__ void cp_async16(void* smem_dst, const void* gmem_src) {
    uint32_t s = (uint32_t)__cvta_generic_to_shared(smem_dst);
    asm volatile("cp.async.cg.shared.global [%0], [%1], 16;\n" :: "r"(s), "l"(gmem_src));
}

// ===========================================================================
// TF32 tensor-core GEMM: C[M,N] = A[M,K] @ B[K,N] + bias[N] (optional ReLU)
// 128x128 block tile, BK=16, 8 warps (2x4), 64x32 per warp via m16n8k8 mma.
// ===========================================================================
#define GAS 20    // As row stride (floats): banks {20*g+tig} conflict-free
#define GBS 136   // Bs row stride (floats): banks {8*tig+g} conflict-free

__global__ __launch_bounds__(256) void gemm_tf32_kernel(
    const float* __restrict__ A, const float* __restrict__ B,
    const float* __restrict__ bias, float* __restrict__ C,
    int M, int N, int K, int relu)
{
    __shared__ float As[2][128][GAS];   // [m][k], 2 stages
    __shared__ float Bs[2][16][GBS];    // [k][n], 2 stages

    const int tid  = threadIdx.x;
    const int bn   = blockIdx.x;
    const int bm   = blockIdx.y;
    const int warp = tid >> 5;
    const int lane = tid & 31;
    const int g    = lane >> 2;
    const int tig  = lane & 3;
    const int wm   = warp >> 2;
    const int wn   = warp & 3;

    float acc[4][4][4];
    #pragma unroll
    for (int mt = 0; mt < 4; mt++)
        #pragma unroll
        for (int nt = 0; nt < 4; nt++)
            #pragma unroll
            for (int r = 0; r < 4; r++) acc[mt][nt][r] = 0.f;

    const int nk = K >> 4;   // BK = 16

    auto prefetch = [&](int kt, int s) {
        #pragma unroll
        for (int i = 0; i < 2; i++) {
            int c = tid * 2 + i;
            int ar = c >> 2, ac = (c & 3) * 4;
            cp_async16(&As[s][ar][ac],
                       A + (size_t)(bm * 128 + ar) * K + kt * 16 + ac);
            int br = c >> 5, bc = (c & 31) * 4;
            cp_async16(&Bs[s][br][bc],
                       B + (size_t)(kt * 16 + br) * N + bn * 128 + bc);
        }
        asm volatile("cp.async.commit_group;\n");
    };

    prefetch(0, 0);

    for (int kt = 0; kt < nk; kt++) {
        const int s = kt & 1;
        if (kt + 1 < nk) {
            prefetch(kt + 1, s ^ 1);
            asm volatile("cp.async.wait_group 1;\n");
        } else {
            asm volatile("cp.async.wait_group 0;\n");
        }
        __syncthreads();

        #pragma unroll
        for (int ks = 0; ks < 16; ks += 8) {
            uint32_t af[4][4], bf[4][2];
            #pragma unroll
            for (int mt = 0; mt < 4; mt++) {
                const int r0 = wm * 64 + mt * 16 + g;
                af[mt][0] = f2tf32(As[s][r0    ][ks + tig]);
                af[mt][1] = f2tf32(As[s][r0 + 8][ks + tig]);
                af[mt][2] = f2tf32(As[s][r0    ][ks + tig + 4]);
                af[mt][3] = f2tf32(As[s][r0 + 8][ks + tig + 4]);
            }
            #pragma unroll
            for (int nt = 0; nt < 4; nt++) {
                const int c0 = wn * 32 + nt * 8 + g;
                bf[nt][0] = f2tf32(Bs[s][ks + tig    ][c0]);
                bf[nt][1] = f2tf32(Bs[s][ks + tig + 4][c0]);
            }
            #pragma unroll
            for (int mt = 0; mt < 4; mt++)
                #pragma unroll
                for (int nt = 0; nt < 4; nt++)
                    mma_tf32(acc[mt][nt], af[mt], bf[nt]);
        }
        __syncthreads();
    }

    #pragma unroll
    for (int mt = 0; mt < 4; mt++) {
        const size_t row0 = (size_t)(bm * 128 + wm * 64 + mt * 16 + g);
        #pragma unroll
        for (int nt = 0; nt < 4; nt++) {
            const int col = bn * 128 + wn * 32 + nt * 8 + 2 * tig;
            const float bv0 = bias[col], bv1 = bias[col + 1];
            float2 r0 = {acc[mt][nt][0] + bv0, acc[mt][nt][1] + bv1};
            float2 r1 = {acc[mt][nt][2] + bv0, acc[mt][nt][3] + bv1};
            if (relu) {
                r0.x = fmaxf(r0.x, 0.f); r0.y = fmaxf(r0.y, 0.f);
                r1.x = fmaxf(r1.x, 0.f); r1.y = fmaxf(r1.y, 0.f);
            }
            *(float2*)&C[row0 * N + col]       = r0;
            *(float2*)&C[(row0 + 8) * N + col] = r1;
        }
    }
}

// ===========================================================================
// Flash attention on tf32 tensor cores.
// 64 queries/block, 4 warps (16 query rows each), KT=32 keys per tile,
// K/V double-buffered via cp.async. Online softmax is register-resident in
// the mma C-fragment layout (row stats via shfl within 4-lane groups).
// Reference math quirk: logits = q.k/d + (1-mask)*(-1e10)/sqrt(d)
// Smem strides: Ks 68 (4g+tig banks), Vs 72 (8tig+g banks), Ps 36.
// ===========================================================================
#define FQT 64
#define FKT 32
#define KSTR 68
#define VSTR 72
#define PSTR 36

__global__ __launch_bounds__(128) void flash_tf32_kernel(
    const float* __restrict__ Q, const float* __restrict__ Kmat,
    const float* __restrict__ V, const int* __restrict__ mask,
    float* __restrict__ O)
{
    __shared__ float Ks[2][FKT][KSTR];    // [kv][d]
    __shared__ float Vs[2][FKT][VSTR];    // [kv][d]
    __shared__ float Ps[FQT][PSTR];       // probs [q][kv]
    __shared__ float madd[2][FKT];

    const int qtile = blockIdx.x;
    const int bh    = blockIdx.y;
    const int b = bh >> 4;
    const int h = bh & 15;
    const int tid  = threadIdx.x;
    const int warp = tid >> 5;
    const int lane = tid & 31;
    const int g    = lane >> 2;
    const int tig  = lane & 3;
    const int w16  = warp * 16;

    const size_t qrow0 = (size_t)b * SEQ + (size_t)qtile * FQT;

    // ---- Q fragments, register-resident (one-time gmem read) ----
    const float* Qb = Q + (qrow0 + w16) * HID + h * DHEAD;
    uint32_t qf[8][4];
    #pragma unroll
    for (int kt = 0; kt < 8; kt++) {
        qf[kt][0] = f2tf32(Qb[(size_t)(g    ) * HID + kt * 8 + tig    ]);
        qf[kt][1] = f2tf32(Qb[(size_t)(g + 8) * HID + kt * 8 + tig    ]);
        qf[kt][2] = f2tf32(Qb[(size_t)(g    ) * HID + kt * 8 + tig + 4]);
        qf[kt][3] = f2tf32(Qb[(size_t)(g + 8) * HID + kt * 8 + tig + 4]);
    }

    float oacc[8][4];
    #pragma unroll
    for (int nt = 0; nt < 8; nt++)
        #pragma unroll
        for (int r = 0; r < 4; r++) oacc[nt][r] = 0.f;

    float m0 = -INFINITY, m1 = -INFINITY, l0 = 0.f, l1 = 0.f;

    const float inv_d = 1.0f / (float)DHEAD;     // combined double scale
    const float inv_s = -1.0e10f / 8.0f;         // add / sqrt(d)

    const float* Kb = Kmat + ((size_t)b * SEQ) * HID + h * DHEAD;
    const float* Vb = V    + ((size_t)b * SEQ) * HID + h * DHEAD;

    auto loadKV = [&](int t0, int s) {
        // K,V tiles: 32 rows x 16 float4 = 512 float4 each; 4 per thread each
        #pragma unroll
        for (int i = 0; i < 4; i++) {
            int idx = tid + 128 * i;
            int r = idx >> 4, c4 = (idx & 15) * 4;
            cp_async16(&Ks[s][r][c4], Kb + (size_t)(t0 + r) * HID + c4);
            cp_async16(&Vs[s][r][c4], Vb + (size_t)(t0 + r) * HID + c4);
        }
        if (tid < FKT)
            madd[s][tid] = (mask[b * SEQ + t0 + tid] != 0) ? 0.f : inv_s;
        asm volatile("cp.async.commit_group;\n");
    };

    loadKV(0, 0);

    const int NT = SEQ / FKT;   // 32 tiles
    for (int t = 0; t < NT; t++) {
        const int s = t & 1;
        if (t + 1 < NT) {
            loadKV((t + 1) * FKT, s ^ 1);
            asm volatile("cp.async.wait_group 1;\n");
        } else {
            asm volatile("cp.async.wait_group 0;\n");
        }
        __syncthreads();

        // ---- S = Q @ K^T for 16x32 warp tile ----
        float sacc[4][4];
        #pragma unroll
        for (int nt = 0; nt < 4; nt++)
            #pragma unroll
            for (int r = 0; r < 4; r++) sacc[nt][r] = 0.f;

        #pragma unroll
        for (int kt = 0; kt < 8; kt++) {
            uint32_t bf[4][2];
            #pragma unroll
            for (int nt = 0; nt < 4; nt++) {
                bf[nt][0] = f2tf32(Ks[s][nt * 8 + g][kt * 8 + tig    ]);
                bf[nt][1] = f2tf32(Ks[s][nt * 8 + g][kt * 8 + tig + 4]);
            }
            #pragma unroll
            for (int nt = 0; nt < 4; nt++)
                mma_tf32(sacc[nt], qf[kt], bf[nt]);
        }

        // scale + mask (cols: nt*8 + 2*tig + {0,1}; rows g / g+8)
        #pragma unroll
        for (int nt = 0; nt < 4; nt++) {
            const int c = nt * 8 + 2 * tig;
            const float ma0 = madd[s][c], ma1 = madd[s][c + 1];
            sacc[nt][0] = sacc[nt][0] * inv_d + ma0;
            sacc[nt][1] = sacc[nt][1] * inv_d + ma1;
            sacc[nt][2] = sacc[nt][2] * inv_d + ma0;
            sacc[nt][3] = sacc[nt][3] * inv_d + ma1;
        }

        // ---- online softmax (rows g and g+8) ----
        float mx0 = -INFINITY, mx1 = -INFINITY;
        #pragma unroll
        for (int nt = 0; nt < 4; nt++) {
            mx0 = fmaxf(mx0, fmaxf(sacc[nt][0], sacc[nt][1]));
            mx1 = fmaxf(mx1, fmaxf(sacc[nt][2], sacc[nt][3]));
        }
        mx0 = fmaxf(mx0, __shfl_xor_sync(0xffffffffu, mx0, 1));
        mx0 = fmaxf(mx0, __shfl_xor_sync(0xffffffffu, mx0, 2));
        mx1 = fmaxf(mx1, __shfl_xor_sync(0xffffffffu, mx1, 1));
        mx1 = fmaxf(mx1, __shfl_xor_sync(0xffffffffu, mx1, 2));

        const float nm0 = fmaxf(m0, mx0);
        const float nm1 = fmaxf(m1, mx1);
        const float al0 = __expf(m0 - nm0);   // -inf -> 0 on first tile
        const float al1 = __expf(m1 - nm1);
        m0 = nm0; m1 = nm1;

        float sum0 = 0.f, sum1 = 0.f;
        #pragma unroll
        for (int nt = 0; nt < 4; nt++) {
            float p0 = __expf(sacc[nt][0] - nm0);
            float p1 = __expf(sacc[nt][1] - nm0);
            float p2 = __expf(sacc[nt][2] - nm1);
            float p3 = __expf(sacc[nt][3] - nm1);
            sum0 += p0 + p1;
            sum1 += p2 + p3;
            const int c = nt * 8 + 2 * tig;
            *(float2*)&Ps[w16 + g    ][c] = make_float2(p0, p1);
            *(float2*)&Ps[w16 + g + 8][c] = make_float2(p2, p3);
        }
        sum0 += __shfl_xor_sync(0xffffffffu, sum0, 1);
        sum0 += __shfl_xor_sync(0xffffffffu, sum0, 2);
        sum1 += __shfl_xor_sync(0xffffffffu, sum1, 1);
        sum1 += __shfl_xor_sync(0xffffffffu, sum1, 2);
        l0 = l0 * al0 + sum0;
        l1 = l1 * al1 + sum1;

        // rescale O accumulators
        #pragma unroll
        for (int nt = 0; nt < 8; nt++) {
            oacc[nt][0] *= al0; oacc[nt][1] *= al0;
            oacc[nt][2] *= al1; oacc[nt][3] *= al1;
        }

        __syncwarp();   // P written by all lanes of this warp, read below

        // ---- O += P @ V ----
        #pragma unroll
        for (int kt = 0; kt < 4; kt++) {
            uint32_t af[4];
            af[0] = f2tf32(Ps[w16 + g    ][kt * 8 + tig    ]);
            af[1] = f2tf32(Ps[w16 + g + 8][kt * 8 + tig    ]);
            af[2] = f2tf32(Ps[w16 + g    ][kt * 8 + tig + 4]);
            af[3] = f2tf32(Ps[w16 + g + 8][kt * 8 + tig + 4]);
            #pragma unroll
            for (int nt = 0; nt < 8; nt++) {
                uint32_t bf2[2];
                bf2[0] = f2tf32(Vs[s][kt * 8 + tig    ][nt * 8 + g]);
                bf2[1] = f2tf32(Vs[s][kt * 8 + tig + 4][nt * 8 + g]);
                mma_tf32(oacc[nt], af, bf2);
            }
        }
        __syncthreads();  // done reading stage s before next loadKV overwrites it
    }

    // ---- normalize + write ----
    const float il0 = 1.0f / l0;
    const float il1 = 1.0f / l1;
    float* Ob = O + (qrow0 + w16) * HID + h * DHEAD;
    #pragma unroll
    for (int nt = 0; nt < 8; nt++) {
        const int c = nt * 8 + 2 * tig;
        *(float2*)&Ob[(size_t)(g    ) * HID + c] =
            make_float2(oacc[nt][0] * il0, oacc[nt][1] * il0);
        *(float2*)&Ob[(size_t)(g + 8) * HID + c] =
            make_float2(oacc[nt][2] * il1, oacc[nt][3] * il1);
    }
}

// ===========================================================================
// Fused residual-add + LayerNorm (unchanged)
// ===========================================================================
__device__ __forceinline__ float block_sum256(float v, float* sh)
{
    const int lane = threadIdx.x & 31;
    const int wid  = threadIdx.x >> 5;
    #pragma unroll
    for (int o = 16; o > 0; o >>= 1) v += __shfl_xor_sync(0xffffffffu, v, o);
    if (lane == 0) sh[wid] = v;
    __syncthreads();
    if (wid == 0) {
        float t = (lane < 8) ? sh[lane] : 0.f;
        #pragma unroll
        for (int o = 4; o > 0; o >>= 1) t += __shfl_xor_sync(0xffffffffu, t, o);
        if (lane == 0) sh[0] = t;
    }
    __syncthreads();
    float r = sh[0];
    __syncthreads();
    return r;
}

__global__ __launch_bounds__(256) void add_ln_kernel(
    const float* __restrict__ a, const float* __restrict__ resid,
    const float* __restrict__ g, const float* __restrict__ b,
    float* __restrict__ out)
{
    __shared__ float sh[32];
    const size_t row = blockIdx.x;
    const int t = threadIdx.x;

    float4 va = ((const float4*)(a + row * HID))[t];
    float4 vr = ((const float4*)(resid + row * HID))[t];
    float4 v = {va.x + vr.x, va.y + vr.y, va.z + vr.z, va.w + vr.w};

    float tot = block_sum256(v.x + v.y + v.z + v.w, sh);
    const float mean = tot * (1.0f / HID);

    float4 d = {v.x - mean, v.y - mean, v.z - mean, v.w - mean};
    float tot2 = block_sum256(d.x*d.x + d.y*d.y + d.z*d.z + d.w*d.w, sh);
    const float inv = rsqrtf(tot2 * (1.0f / HID) + 1e-5f);

    float4 vg = ((const float4*)g)[t];
    float4 vb = ((const float4*)b)[t];
    float4 o;
    o.x = vg.x * d.x * inv + vb.x;
    o.y = vg.y * d.y * inv + vb.y;
    o.z = vg.z * d.z * inv + vb.z;
    o.w = vg.w * d.w * inv + vb.w;
    ((float4*)(out + row * HID))[t] = o;
}

// ===========================================================================
// Host orchestration
// ===========================================================================
extern "C" void kernel_launch(void* const* d_in, const int* in_sizes, int n_in,
                              void* d_out, int out_size)
{
    (void)in_sizes; (void)n_in; (void)out_size;

    const float* x     = (const float*)d_in[0];
    const int*   smask = (const int*)  d_in[1];
    const float* cx    = (const float*)d_in[2];
    const int*   cmask = (const int*)  d_in[3];
    const float* sWq = (const float*)d_in[5],  *sbq = (const float*)d_in[6];
    const float* sWk = (const float*)d_in[7],  *sbk = (const float*)d_in[8];
    const float* sWv = (const float*)d_in[9],  *sbv = (const float*)d_in[10];
    const float* sWo = (const float*)d_in[11], *sbo = (const float*)d_in[12];
    const float* cWq = (const float*)d_in[13], *cbq = (const float*)d_in[14];
    const float* cWk = (const float*)d_in[15], *cbk = (const float*)d_in[16];
    const float* cWv = (const float*)d_in[17], *cbv = (const float*)d_in[18];
    const float* cWo = (const float*)d_in[19], *cbo = (const float*)d_in[20];
    const float* g   = (const float*)d_in[21], *bb  = (const float*)d_in[22];
    const float* W1  = (const float*)d_in[23], *b1  = (const float*)d_in[24];
    const float* W2  = (const float*)d_in[25], *b2  = (const float*)d_in[26];
    float* out = (float*)d_out;

    float* base = nullptr;
    cudaGetSymbolAddress((void**)&base, g_scratch);
    float* q   = base;
    float* k   = base + 1 * NELEM;
    float* v   = base + 2 * NELEM;
    float* att = base + 3 * NELEM;
    float* tmp = base + 4 * NELEM;
    float* san = base + 5 * NELEM;
    float* h2  = base + 6 * NELEM;
    float* ff1 = base + 7 * NELEM;   // 4x wide

    const dim3 gHH(HID / 128, NTOK / 128);          // (8, 32)
    const dim3 gF1(4 * HID / 128, NTOK / 128);      // (32, 32)
    const dim3 gF2(HID / 128, NTOK / 128);          // (8, 32)
    const dim3 gFl(SEQ / FQT, BATCH * NHEAD);       // (16, 64)

    // ---- Self attention ----
    gemm_tf32_kernel<<<gHH, 256>>>(x, sWq, sbq, q, NTOK, HID, HID, 0);
    gemm_tf32_kernel<<<gHH, 256>>>(x, sWk, sbk, k, NTOK, HID, HID, 0);
    gemm_tf32_kernel<<<gHH, 256>>>(x, sWv, sbv, v, NTOK, HID, HID, 0);
    flash_tf32_kernel<<<gFl, 128>>>(q, k, v, smask, att);
    gemm_tf32_kernel<<<gHH, 256>>>(att, sWo, sbo, tmp, NTOK, HID, HID, 0);
    add_ln_kernel<<<NTOK, 256>>>(tmp, x, g, bb, san);

    // ---- Cross attention ----
    gemm_tf32_kernel<<<gHH, 256>>>(san, cWq, cbq, q, NTOK, HID, HID, 0);
    gemm_tf32_kernel<<<gHH, 256>>>(cx,  cWk, cbk, k, NTOK, HID, HID, 0);
    gemm_tf32_kernel<<<gHH, 256>>>(cx,  cWv, cbv, v, NTOK, HID, HID, 0);
    flash_tf32_kernel<<<gFl, 128>>>(q, k, v, cmask, att);
    gemm_tf32_kernel<<<gHH, 256>>>(att, cWo, cbo, tmp, NTOK, HID, HID, 0);
    // residual uses ORIGINAL hidden_states (matches reference)
    add_ln_kernel<<<NTOK, 256>>>(tmp, x, g, bb, h2);

    // ---- FFN ----
    gemm_tf32_kernel<<<gF1, 256>>>(h2,  W1, b1, ff1, NTOK, 4 * HID, HID, 1);
    gemm_tf32_kernel<<<gF2, 256>>>(ff1, W2, b2, tmp, NTOK, HID, 4 * HID, 0);
    add_ln_kernel<<<NTOK, 256>>>(tmp, h2, g, bb, out);
}